// round 15
// baseline (speedup 1.0000x reference)
#include <cuda_runtime.h>
#include <cuda_bf16.h>
#include <math.h>
#include <stdint.h>

// Problem dims (fixed by dataset)
static constexpr int NMAX = 50000;
static constexpr int D    = 64;
static constexpr int C    = 64;   // embed out
static constexpr int K    = 500;  // assign out / clusters
static constexpr int KP   = 512;  // padded K
static constexpr int EMAX = 800000;
static constexpr int SCAN_B = 1024;
static constexpr int NSCANB = (NMAX + SCAN_B - 1) / SCAN_B;

// ---------------- scratch (device globals; no allocations allowed) ----------
// CSR pair: [0] = row-CSR (out-edges, stores col) for AS gather
//           [1] = col-CSR (in-edges, stores row) for px gather
__device__ float g_dinv[NMAX];
__device__ float g_c   [NMAX];
__device__ int   g_cnt [2][NMAX];
__device__ int   g_off [2][NMAX + 1];
__device__ int   g_cur [2][NMAX];
__device__ int   g_eidx[2][EMAX];
__device__ int   g_bsum[2][NSCANB];
__device__ int   g_bpre[2][NSCANB];
__device__ float g_px  [NMAX * D];                    // P @ x (f32)
__device__ float g_zE  [NMAX * C];                    // GCN(embed) f32
__device__ __nv_bfloat16 g_Sb [(long)NMAX * KP];      // softmax bf16, padded
__device__ __nv_bfloat16 g_ASb[(long)NMAX * KP];      // A @ S bf16, padded

// fused-kernel smem layout (bytes)
static constexpr int XS_OFF  = 0;                      // float[64][66]
static constexpr int WS_OFF  = XS_OFF + 64 * 66 * 4;   // float[64][128]
static constexpr int SE_OFF  = WS_OFF + 64 * 128 * 4;  // float[64][516]
static constexpr int BS_OFF  = SE_OFF + 64 * 516 * 4;  // float[512]
static constexpr int SUM_OFF = BS_OFF + 512 * 4;       // float[64][16]
static constexpr int INV_OFF = SUM_OFF + 64 * 16 * 4;  // float[64]
static constexpr int SMEM_FUSED = INV_OFF + 64 * 4;    // ~188 KB

// ---------------- init: zero out + both cnt arrays --------------------------
__global__ void k_init(float* out, int total, int n) {
    int i = blockIdx.x * blockDim.x + threadIdx.x;
    if (i < total) out[i] = 0.0f;
    if (i < n) { g_cnt[0][i] = 0; g_cnt[1][i] = 0; }
}

__global__ void k_cnt_both(const int* __restrict__ row, const int* __restrict__ col,
                           int e) {
    int i = blockIdx.x * blockDim.x + threadIdx.x;
    if (i < e) {
        atomicAdd(&g_cnt[0][row[i]], 1);
        atomicAdd(&g_cnt[1][col[i]], 1);
    }
}

// ---------------- decoupled 3-phase exclusive scan (both arrays) ------------
__global__ __launch_bounds__(1024) void k_scan1(int n) {
    __shared__ int sm[1024];
    int a = blockIdx.y;
    int i = blockIdx.x * SCAN_B + threadIdx.x;
    int v = (i < n) ? g_cnt[a][i] : 0;
    if (a == 0 && i < n) g_dinv[i] = rsqrtf((float)v + 1.0f);
    sm[threadIdx.x] = v;
    __syncthreads();
#pragma unroll
    for (int off = 1; off < 1024; off <<= 1) {
        int u = (threadIdx.x >= off) ? sm[threadIdx.x - off] : 0;
        __syncthreads();
        sm[threadIdx.x] += u;
        __syncthreads();
    }
    if (i < n) g_off[a][i] = sm[threadIdx.x] - v;
    if (threadIdx.x == 1023) g_bsum[a][blockIdx.x] = sm[1023];
}

__global__ __launch_bounds__(64) void k_scan2(int n) {
    __shared__ int sm[64];
    int a = blockIdx.x;
    int t = threadIdx.x;
    int v = (t < NSCANB) ? g_bsum[a][t] : 0;
    sm[t] = v;
    __syncthreads();
#pragma unroll
    for (int off = 1; off < 64; off <<= 1) {
        int u = (t >= off) ? sm[t - off] : 0;
        __syncthreads();
        sm[t] += u;
        __syncthreads();
    }
    if (t < NSCANB) g_bpre[a][t] = sm[t] - v;
    if (t == 63) g_off[a][n] = sm[63];
}

__global__ __launch_bounds__(1024) void k_scan3(int n) {
    int a = blockIdx.y;
    int i = blockIdx.x * SCAN_B + threadIdx.x;
    if (i < n) {
        int o = g_off[a][i] + g_bpre[a][blockIdx.x];
        g_off[a][i] = o;
        g_cur[a][i] = o;
    }
}

// fill both CSRs in one pass
__global__ void k_fill_both(const int* __restrict__ row, const int* __restrict__ col,
                            int e) {
    int i = blockIdx.x * blockDim.x + threadIdx.x;
    if (i < e) {
        int r = row[i], c = col[i];
        int p0 = atomicAdd(&g_cur[0][r], 1);
        g_eidx[0][p0] = c;
        int p1 = atomicAdd(&g_cur[1][c], 1);
        g_eidx[1][p1] = r;
    }
}

// ---------------- px = P @ x via col-CSR gather (+ self term, + c coef) -----
__global__ __launch_bounds__(256) void k_gather_px(const float* __restrict__ x, int n) {
    int node = blockIdx.x * 16 + (threadIdx.x >> 4);
    if (node >= n) return;
    int lane = threadIdx.x & 15;
    float dv = g_dinv[node];
    int beg = g_off[1][node], end = g_off[1][node + 1];

    float4 acc = __ldg(reinterpret_cast<const float4*>(x + (long)node * D) + lane);
    acc.x *= dv; acc.y *= dv; acc.z *= dv; acc.w *= dv;
    float csum = dv;

    int e = beg;
    for (; e + 1 < end; e += 2) {
        int r0 = __ldg(&g_eidx[1][e]);
        int r1 = __ldg(&g_eidx[1][e + 1]);
        float w0 = __ldg(&g_dinv[r0]);
        float w1 = __ldg(&g_dinv[r1]);
        float4 v0 = __ldg(reinterpret_cast<const float4*>(x + (long)r0 * D) + lane);
        float4 v1 = __ldg(reinterpret_cast<const float4*>(x + (long)r1 * D) + lane);
        acc.x += w0 * v0.x + w1 * v1.x;
        acc.y += w0 * v0.y + w1 * v1.y;
        acc.z += w0 * v0.z + w1 * v1.z;
        acc.w += w0 * v0.w + w1 * v1.w;
        csum += w0 + w1;
    }
    if (e < end) {
        int r0 = __ldg(&g_eidx[1][e]);
        float w0 = __ldg(&g_dinv[r0]);
        float4 v0 = __ldg(reinterpret_cast<const float4*>(x + (long)r0 * D) + lane);
        acc.x += w0 * v0.x; acc.y += w0 * v0.y;
        acc.z += w0 * v0.z; acc.w += w0 * v0.w;
        csum += w0;
    }

    float4 o = make_float4(dv * acc.x, dv * acc.y, dv * acc.z, dv * acc.w);
    reinterpret_cast<float4*>(g_px + (long)node * D)[lane] = o;
    if (lane == 0) g_c[node] = dv * csum;
}

// ---------------- zE = px @ We + c*be^T  (f32x2 packed; f32 out) ------------
__global__ __launch_bounds__(256) void k_xw0(const float* __restrict__ W,
                                             const float* __restrict__ b, int n) {
    constexpr int TN = 4, PADX = 66;
    __shared__ float xs[64][PADX];
    __shared__ float ws[64][64];

    const int n0 = blockIdx.y * 64;
    const int tid = threadIdx.x;

    for (int i = tid; i < 64 * 16; i += 256) {
        int nn = i >> 4, k4 = (i & 15) << 2;
        float4 v = make_float4(0.f, 0.f, 0.f, 0.f);
        if (n0 + nn < n)
            v = *reinterpret_cast<const float4*>(g_px + (long)(n0 + nn) * D + k4);
        xs[k4 + 0][nn] = v.x; xs[k4 + 1][nn] = v.y;
        xs[k4 + 2][nn] = v.z; xs[k4 + 3][nn] = v.w;
    }
    for (int i = tid; i < 64 * 16; i += 256) {
        int k = i >> 4, c4 = (i & 15) << 2;
        *reinterpret_cast<float4*>(&ws[k][c4]) =
            *reinterpret_cast<const float4*>(W + k * C + c4);
    }
    __syncthreads();

    const int txm = tid & 15;
    const int tyn = tid >> 4;

    unsigned long long acc[2][TN];
#pragma unroll
    for (int p = 0; p < 2; p++)
#pragma unroll
        for (int j = 0; j < TN; j++) acc[p][j] = 0ull;

    uint32_t sX = (uint32_t)__cvta_generic_to_shared((void*)&xs[0][0]);

#pragma unroll 4
    for (int k = 0; k < 64; k++) {
        unsigned long long a2[2];
#pragma unroll
        for (int p = 0; p < 2; p++) {
            uint32_t addr = sX + ((uint32_t)(k * PADX + txm * 4 + p * 2) << 2);
            asm volatile("ld.shared.b64 %0, [%1];" : "=l"(a2[p]) : "r"(addr));
        }
        float bv[TN];
        float4 b4 = *reinterpret_cast<const float4*>(&ws[k][tyn * TN]);
        bv[0] = b4.x; bv[1] = b4.y; bv[2] = b4.z; bv[3] = b4.w;
#pragma unroll
        for (int j = 0; j < TN; j++) {
            unsigned long long bb;
            asm("mov.b64 %0, {%1, %2};" : "=l"(bb) : "f"(bv[j]), "f"(bv[j]));
#pragma unroll
            for (int p = 0; p < 2; p++)
                asm("fma.rn.f32x2 %0, %1, %2, %0;"
                    : "+l"(acc[p][j]) : "l"(a2[p]), "l"(bb));
        }
    }

#pragma unroll
    for (int p = 0; p < 2; p++) {
        int nn = n0 + txm * 4 + p * 2;
        float cv0 = (nn < n) ? g_c[nn] : 0.f;
        float cv1 = (nn + 1 < n) ? g_c[nn + 1] : 0.f;
#pragma unroll
        for (int j = 0; j < TN; j++) {
            int cc = tyn * TN + j;
            float lo, hi;
            asm("mov.b64 {%0, %1}, %2;" : "=f"(lo), "=f"(hi) : "l"(acc[p][j]));
            float bj = __ldg(&b[cc]);
            if (nn < n)     g_zE[(long)nn * C + cc] = lo + cv0 * bj;
            if (nn + 1 < n) g_zE[(long)(nn + 1) * C + cc] = hi + cv1 * bj;
        }
    }
}

// ---------------- FUSED: S = softmax(px @ Wa + c*ba^T) -> g_Sb (bf16) -------
// One block = 64 nodes x all 512 cols. Logits computed in 4 chunks of 128
// cols (f32x2 math identical to the unfused GEMM), exp'd into smem, row-sums
// reduced in-block, normalized bf16 written straight to g_Sb. No f32 logits
// buffer ever touches DRAM.
__global__ __launch_bounds__(256) void k_xw1_sm(const float* __restrict__ W,
                                                const float* __restrict__ b, int n) {
    constexpr float LOG2E = 1.4426950408889634f;
    constexpr int PADX = 66, PADS = 516;
    extern __shared__ char smem[];
    float (*xs)[PADX] = reinterpret_cast<float(*)[PADX]>(smem + XS_OFF);
    float (*ws)[128]  = reinterpret_cast<float(*)[128]>(smem + WS_OFF);
    float (*se)[PADS] = reinterpret_cast<float(*)[PADS]>(smem + SE_OFF);
    float* bsm        = reinterpret_cast<float*>(smem + BS_OFF);
    float (*sums)[16] = reinterpret_cast<float(*)[16]>(smem + SUM_OFF);
    float* sinv       = reinterpret_cast<float*>(smem + INV_OFF);

    const int n0 = blockIdx.x * 64;
    const int tid = threadIdx.x;
    const int txm = tid & 15;
    const int tyn = tid >> 4;

    // stage xs (transposed px tile) + scaled bias
    for (int i = tid; i < 64 * 16; i += 256) {
        int nn = i >> 4, k4 = (i & 15) << 2;
        float4 v = make_float4(0.f, 0.f, 0.f, 0.f);
        if (n0 + nn < n)
            v = *reinterpret_cast<const float4*>(g_px + (long)(n0 + nn) * D + k4);
        xs[k4 + 0][nn] = v.x; xs[k4 + 1][nn] = v.y;
        xs[k4 + 2][nn] = v.z; xs[k4 + 3][nn] = v.w;
    }
    for (int i = tid; i < 512; i += 256)
        bsm[i] = (i < K) ? __ldg(&b[i]) * LOG2E : 0.f;

    // per-thread node coefficients (4 consecutive nodes)
    float cvv[4];
    {
        int nb = n0 + txm * 4;
#pragma unroll
        for (int i = 0; i < 4; i++)
            cvv[i] = (nb + i < n) ? __ldg(&g_c[nb + i]) : 0.f;
    }

    uint32_t sX = (uint32_t)__cvta_generic_to_shared((void*)&xs[0][0]);
    float rs[4] = {0.f, 0.f, 0.f, 0.f};

    __syncthreads();

    for (int chunk = 0; chunk < 4; chunk++) {
        const int c0 = chunk * 128;
        // stage ws chunk (W * log2e)
        for (int i = tid; i < 64 * 32; i += 256) {
            int k = i >> 5, c4 = (i & 31) << 2;
            int cc = c0 + c4;
            float4 v = make_float4(0.f, 0.f, 0.f, 0.f);
            if (cc + 3 < K) {
                v = *reinterpret_cast<const float4*>(W + k * K + cc);
            } else {
                if (cc + 0 < K) v.x = W[k * K + cc + 0];
                if (cc + 1 < K) v.y = W[k * K + cc + 1];
                if (cc + 2 < K) v.z = W[k * K + cc + 2];
            }
            v.x *= LOG2E; v.y *= LOG2E; v.z *= LOG2E; v.w *= LOG2E;
            *reinterpret_cast<float4*>(&ws[k][c4]) = v;
        }
        __syncthreads();

        unsigned long long acc[2][8];
#pragma unroll
        for (int p = 0; p < 2; p++)
#pragma unroll
            for (int j = 0; j < 8; j++) acc[p][j] = 0ull;

#pragma unroll 4
        for (int k = 0; k < 64; k++) {
            unsigned long long a2[2];
#pragma unroll
            for (int p = 0; p < 2; p++) {
                uint32_t addr = sX + ((uint32_t)(k * PADX + txm * 4 + p * 2) << 2);
                asm volatile("ld.shared.b64 %0, [%1];" : "=l"(a2[p]) : "r"(addr));
            }
            float bv[8];
#pragma unroll
            for (int j4 = 0; j4 < 2; j4++) {
                float4 b4 = *reinterpret_cast<const float4*>(&ws[k][tyn * 8 + j4 * 4]);
                bv[j4 * 4 + 0] = b4.x; bv[j4 * 4 + 1] = b4.y;
                bv[j4 * 4 + 2] = b4.z; bv[j4 * 4 + 3] = b4.w;
            }
#pragma unroll
            for (int j = 0; j < 8; j++) {
                unsigned long long bb;
                asm("mov.b64 %0, {%1, %2};" : "=l"(bb) : "f"(bv[j]), "f"(bv[j]));
#pragma unroll
                for (int p = 0; p < 2; p++)
                    asm("fma.rn.f32x2 %0, %1, %2, %0;"
                        : "+l"(acc[p][j]) : "l"(a2[p]), "l"(bb));
            }
        }

        // epilogue: exp2(logit + c*b), store to se, accumulate row sums
        float val[4][8];
#pragma unroll
        for (int p = 0; p < 2; p++)
#pragma unroll
            for (int j = 0; j < 8; j++) {
                int col = c0 + tyn * 8 + j;
                float lo, hi;
                asm("mov.b64 {%0, %1}, %2;" : "=f"(lo), "=f"(hi) : "l"(acc[p][j]));
                float bj = bsm[col];
                float t0 = lo + cvv[p * 2] * bj;
                float t1 = hi + cvv[p * 2 + 1] * bj;
                float e0, e1;
                asm("ex2.approx.ftz.f32 %0, %1;" : "=f"(e0) : "f"(t0));
                asm("ex2.approx.ftz.f32 %0, %1;" : "=f"(e1) : "f"(t1));
                if (col >= K) { e0 = 0.f; e1 = 0.f; }
                val[p * 2][j] = e0;
                val[p * 2 + 1][j] = e1;
                rs[p * 2] += e0;
                rs[p * 2 + 1] += e1;
            }
#pragma unroll
        for (int i = 0; i < 4; i++) {
            int node_l = txm * 4 + i;
            int col = c0 + tyn * 8;
            *reinterpret_cast<float4*>(&se[node_l][col]) =
                make_float4(val[i][0], val[i][1], val[i][2], val[i][3]);
            *reinterpret_cast<float4*>(&se[node_l][col + 4]) =
                make_float4(val[i][4], val[i][5], val[i][6], val[i][7]);
        }
        __syncthreads();   // ws reuse + se visibility
    }

    // row-sum reduction
#pragma unroll
    for (int i = 0; i < 4; i++) sums[txm * 4 + i][tyn] = rs[i];
    __syncthreads();
    if (tid < 64) {
        float s = 0.f;
#pragma unroll
        for (int j = 0; j < 16; j++) s += sums[tid][j];
        sinv[tid] = 1.0f / s;
    }
    __syncthreads();

    // normalize + bf16 write (4 threads per node, 128 cols each)
    {
        int node_l = tid >> 2;
        int seg = tid & 3;
        int node = n0 + node_l;
        if (node < n) {
            float iv = sinv[node_l];
            uint4* dst = reinterpret_cast<uint4*>(g_Sb + (long)node * KP) + seg * 16;
#pragma unroll
            for (int u = 0; u < 16; u++) {
                int col = seg * 128 + u * 8;
                float4 a = *reinterpret_cast<float4*>(&se[node_l][col]);
                float4 d = *reinterpret_cast<float4*>(&se[node_l][col + 4]);
                __nv_bfloat162 r0 = __floats2bfloat162_rn(a.x * iv, a.y * iv);
                __nv_bfloat162 r1 = __floats2bfloat162_rn(a.z * iv, a.w * iv);
                __nv_bfloat162 r2 = __floats2bfloat162_rn(d.x * iv, d.y * iv);
                __nv_bfloat162 r3 = __floats2bfloat162_rn(d.z * iv, d.w * iv);
                uint4 o;
                o.x = *reinterpret_cast<uint32_t*>(&r0);
                o.y = *reinterpret_cast<uint32_t*>(&r1);
                o.z = *reinterpret_cast<uint32_t*>(&r2);
                o.w = *reinterpret_cast<uint32_t*>(&r3);
                dst[u] = o;
            }
        }
    }
}

// ---------------- AS[i] = sum_{e in out(i)} Sb[col_e]  (bf16 in/out) --------
__global__ __launch_bounds__(256) void k_AS_gather(int n) {
    int node = blockIdx.x * 4 + (threadIdx.x >> 6);
    if (node >= n) return;
    int c = threadIdx.x & 63;
    int beg = g_off[0][node], end = g_off[0][node + 1];

    float a[8] = {};
    const uint4* base = reinterpret_cast<const uint4*>(g_Sb);

    int e = beg;
    for (; e + 3 < end; e += 4) {
        int s0 = __ldg(&g_eidx[0][e]);
        int s1 = __ldg(&g_eidx[0][e + 1]);
        int s2 = __ldg(&g_eidx[0][e + 2]);
        int s3 = __ldg(&g_eidx[0][e + 3]);
        uint4 v0 = __ldg(&base[(long)s0 * (KP / 8) + c]);
        uint4 v1 = __ldg(&base[(long)s1 * (KP / 8) + c]);
        uint4 v2 = __ldg(&base[(long)s2 * (KP / 8) + c]);
        uint4 v3 = __ldg(&base[(long)s3 * (KP / 8) + c]);
#pragma unroll
        for (int q = 0; q < 4; q++) {
            uint32_t w0 = (&v0.x)[q], w1 = (&v1.x)[q];
            uint32_t w2 = (&v2.x)[q], w3 = (&v3.x)[q];
            float2 f0 = __bfloat1622float2(*reinterpret_cast<__nv_bfloat162*>(&w0));
            float2 f1 = __bfloat1622float2(*reinterpret_cast<__nv_bfloat162*>(&w1));
            float2 f2 = __bfloat1622float2(*reinterpret_cast<__nv_bfloat162*>(&w2));
            float2 f3 = __bfloat1622float2(*reinterpret_cast<__nv_bfloat162*>(&w3));
            a[q * 2 + 0] += (f0.x + f1.x) + (f2.x + f3.x);
            a[q * 2 + 1] += (f0.y + f1.y) + (f2.y + f3.y);
        }
    }
    for (; e < end; e++) {
        int s0 = __ldg(&g_eidx[0][e]);
        uint4 v0 = __ldg(&base[(long)s0 * (KP / 8) + c]);
#pragma unroll
        for (int q = 0; q < 4; q++) {
            uint32_t w0 = (&v0.x)[q];
            float2 f0 = __bfloat1622float2(*reinterpret_cast<__nv_bfloat162*>(&w0));
            a[q * 2 + 0] += f0.x;
            a[q * 2 + 1] += f0.y;
        }
    }

    uint4 o;
#pragma unroll
    for (int q = 0; q < 4; q++) {
        __nv_bfloat162 r = __floats2bfloat162_rn(a[q * 2], a[q * 2 + 1]);
        (&o.x)[q] = *reinterpret_cast<uint32_t*>(&r);
    }
    reinterpret_cast<uint4*>(g_ASb)[(long)node * (KP / 8) + c] = o;
}

// ---------------- next_X = S^T @ zE  (bf16 S staged to f32, f32x2 math) -----
__global__ __launch_bounds__(256) void k_stm0(float* __restrict__ out, int n,
                                              int nPerSplit) {
    constexpr int BN = 64, TN = 4, BM = 128, BK = 32;
    __shared__ float Ss[BK][BM];
    __shared__ float Ms[BK][BN];

    const int m0 = blockIdx.y * BM;
    const int nStart = blockIdx.z * nPerSplit;
    const int nEnd = min(n, nStart + nPerSplit);
    const int tid = threadIdx.x;
    const int txm = tid & 15;
    const int tyn = tid >> 4;

    unsigned long long acc[2][2][TN];
#pragma unroll
    for (int a = 0; a < 2; a++)
#pragma unroll
        for (int p = 0; p < 2; p++)
#pragma unroll
            for (int j = 0; j < TN; j++) acc[a][p][j] = 0ull;

    uint32_t sS = (uint32_t)__cvta_generic_to_shared((void*)&Ss[0][0]);

    for (int nb = nStart; nb < nEnd; nb += BK) {
        for (int i = tid; i < BK * (BM / 8); i += 256) {
            int r = i >> 4, q = i & 15;
            int kk = nb + r;
            uint4 v = make_uint4(0, 0, 0, 0);
            if (kk < nEnd)
                v = *reinterpret_cast<const uint4*>(g_Sb + (long)kk * KP + m0 + q * 8);
            float fx[8];
#pragma unroll
            for (int w = 0; w < 4; w++) {
                float2 ff = __bfloat1622float2(
                    *reinterpret_cast<__nv_bfloat162*>(&(&v.x)[w]));
                fx[w * 2] = ff.x; fx[w * 2 + 1] = ff.y;
            }
            *reinterpret_cast<float4*>(&Ss[r][q * 8]) =
                make_float4(fx[0], fx[1], fx[2], fx[3]);
            *reinterpret_cast<float4*>(&Ss[r][q * 8 + 4]) =
                make_float4(fx[4], fx[5], fx[6], fx[7]);
        }
        for (int i = tid; i < BK * (BN / 4); i += 256) {
            int r = i / (BN / 4);
            int c4 = i % (BN / 4);
            int kk = nb + r;
            float4 v = make_float4(0.f, 0.f, 0.f, 0.f);
            if (kk < nEnd)
                v = *reinterpret_cast<const float4*>(g_zE + (long)kk * C + (c4 << 2));
            *reinterpret_cast<float4*>(&Ms[r][c4 << 2]) = v;
        }
        __syncthreads();

#pragma unroll 8
        for (int kk = 0; kk < BK; kk++) {
            unsigned long long a2[2][2];
#pragma unroll
            for (int ch = 0; ch < 2; ch++)
#pragma unroll
                for (int p = 0; p < 2; p++) {
                    uint32_t addr = sS + ((kk * BM + ch * 64 + txm * 4 + p * 2) << 2);
                    asm volatile("ld.shared.b64 %0, [%1];" : "=l"(a2[ch][p]) : "r"(addr));
                }
            float bv[TN];
            float4 b4 = *reinterpret_cast<const float4*>(&Ms[kk][tyn * TN]);
            bv[0] = b4.x; bv[1] = b4.y; bv[2] = b4.z; bv[3] = b4.w;
#pragma unroll
            for (int j = 0; j < TN; j++) {
                unsigned long long bb;
                asm("mov.b64 %0, {%1, %2};" : "=l"(bb) : "f"(bv[j]), "f"(bv[j]));
#pragma unroll
                for (int ch = 0; ch < 2; ch++)
#pragma unroll
                    for (int p = 0; p < 2; p++)
                        asm("fma.rn.f32x2 %0, %1, %2, %0;"
                            : "+l"(acc[ch][p][j]) : "l"(a2[ch][p]), "l"(bb));
            }
        }
        __syncthreads();
    }

#pragma unroll
    for (int ch = 0; ch < 2; ch++)
#pragma unroll
        for (int p = 0; p < 2; p++)
#pragma unroll
            for (int j = 0; j < TN; j++) {
                float lo, hi;
                asm("mov.b64 {%0, %1}, %2;" : "=f"(lo), "=f"(hi) : "l"(acc[ch][p][j]));
                int m = m0 + ch * 64 + txm * 4 + p * 2;
                int nn = tyn * TN + j;
                if (m < K)     atomicAdd(&out[(long)m * C + nn], lo);
                if (m + 1 < K) atomicAdd(&out[(long)(m + 1) * C + nn], hi);
            }
}

// ---------------- next_A = S^T @ AS  (bf16 mma.sync, split-K) ---------------
__global__ __launch_bounds__(256) void k_stm1(float* __restrict__ out, int n,
                                              int nPerSplit) {
    constexpr int PAD = 136;
    __shared__ __align__(16) __nv_bfloat16 As[32][PAD];
    __shared__ __align__(16) __nv_bfloat16 Bs[32][PAD];

    const int m0 = blockIdx.y * 128;
    const int n0 = blockIdx.x * 128;
    const int nStart = blockIdx.z * nPerSplit;
    const int nEnd = min(n, nStart + nPerSplit);
    const int tid = threadIdx.x;
    const int wid = tid >> 5, lane = tid & 31;
    const int wm = wid & 1, wn = wid >> 1;

    float acc[4][4][4] = {};

    uint32_t sA = (uint32_t)__cvta_generic_to_shared((void*)&As[0][0]);
    uint32_t sB = (uint32_t)__cvta_generic_to_shared((void*)&Bs[0][0]);

    for (int k0 = nStart; k0 < nEnd; k0 += 32) {
#pragma unroll
        for (int i = tid; i < 32 * 16; i += 256) {
            int r = i >> 4, q = i & 15;
            int kk = k0 + r;
            uint4 v = make_uint4(0, 0, 0, 0);
            if (kk < nEnd)
                v = *reinterpret_cast<const uint4*>(g_Sb + (long)kk * KP + m0 + q * 8);
            *reinterpret_cast<uint4*>(&As[r][q * 8]) = v;
        }
#pragma unroll
        for (int i = tid; i < 32 * 16; i += 256) {
            int r = i >> 4, q = i & 15;
            int kk = k0 + r;
            uint4 v = make_uint4(0, 0, 0, 0);
            if (kk < nEnd)
                v = *reinterpret_cast<const uint4*>(g_ASb + (long)kk * KP + n0 + q * 8);
            *reinterpret_cast<uint4*>(&Bs[r][q * 8]) = v;
        }
        __syncthreads();

#pragma unroll
        for (int s = 0; s < 2; s++) {
            uint32_t af[4][4];
            int ra = s * 16 + (lane & 7) + ((lane >> 4) << 3);
            int ca = wm * 64 + (((lane >> 3) & 1) << 3);
#pragma unroll
            for (int t = 0; t < 4; t++) {
                uint32_t addr = sA + (uint32_t)(ra * PAD + ca + t * 16) * 2;
                asm volatile("ldmatrix.sync.aligned.m8n8.x4.trans.shared.b16 "
                             "{%0,%1,%2,%3}, [%4];"
                             : "=r"(af[t][0]), "=r"(af[t][1]), "=r"(af[t][2]), "=r"(af[t][3])
                             : "r"(addr));
            }
            uint32_t bfr[2][4];
            int rb = s * 16 + (lane & 7) + (((lane >> 3) & 1) << 3);
            int cb = wn * 32 + ((lane >> 4) << 3);
#pragma unroll
            for (int g = 0; g < 2; g++) {
                uint32_t addr = sB + (uint32_t)(rb * PAD + cb + g * 16) * 2;
                asm volatile("ldmatrix.sync.aligned.m8n8.x4.trans.shared.b16 "
                             "{%0,%1,%2,%3}, [%4];"
                             : "=r"(bfr[g][0]), "=r"(bfr[g][1]), "=r"(bfr[g][2]), "=r"(bfr[g][3])
                             : "r"(addr));
            }
#pragma unroll
            for (int t = 0; t < 4; t++)
#pragma unroll
                for (int j = 0; j < 4; j++) {
                    uint32_t b0 = bfr[j >> 1][(j & 1) * 2];
                    uint32_t b1 = bfr[j >> 1][(j & 1) * 2 + 1];
                    asm volatile(
                        "mma.sync.aligned.m16n8k16.row.col.f32.bf16.bf16.f32 "
                        "{%0,%1,%2,%3}, {%4,%5,%6,%7}, {%8,%9}, {%0,%1,%2,%3};"
                        : "+f"(acc[t][j][0]), "+f"(acc[t][j][1]),
                          "+f"(acc[t][j][2]), "+f"(acc[t][j][3])
                        : "r"(af[t][0]), "r"(af[t][1]), "r"(af[t][2]), "r"(af[t][3]),
                          "r"(b0), "r"(b1));
                }
        }
        __syncthreads();
    }

#pragma unroll
    for (int t = 0; t < 4; t++) {
        int mA = m0 + wm * 64 + t * 16 + (lane >> 2);
#pragma unroll
        for (int j = 0; j < 4; j++) {
            int nn = n0 + wn * 32 + j * 8 + (lane & 3) * 2;
            if (nn < K) {
                if (mA < K)     atomicAdd(&out[(long)mA * K + nn], acc[t][j][0]);
                if (mA + 8 < K) atomicAdd(&out[(long)(mA + 8) * K + nn], acc[t][j][2]);
            }
            if (nn + 1 < K) {
                if (mA < K)     atomicAdd(&out[(long)mA * K + nn + 1], acc[t][j][1]);
                if (mA + 8 < K) atomicAdd(&out[(long)(mA + 8) * K + nn + 1], acc[t][j][3]);
            }
        }
    }
}

// ---------------- launch -----------------------------------------------------
extern "C" void kernel_launch(void* const* d_in, const int* in_sizes, int n_in,
                              void* d_out, int out_size) {
    const float* x  = (const float*)d_in[0];
    const int*   ei = (const int*)d_in[1];
    const float* We = (const float*)d_in[2];
    const float* be = (const float*)d_in[3];
    const float* Wa = (const float*)d_in[4];
    const float* ba = (const float*)d_in[5];
    float* out = (float*)d_out;

    int n = in_sizes[0] / D;
    int e = in_sizes[1] / 2;
    const int* row = ei;       // source j
    const int* col = ei + e;   // target i

    // allow large dynamic smem for the fused kernel (host-side config; not a
    // stream op, safe under graph capture)
    cudaFuncSetAttribute(k_xw1_sm, cudaFuncAttributeMaxDynamicSharedMemorySize,
                         SMEM_FUSED);

    // init: zero output + both cnt arrays
    {
        int total = out_size > n ? out_size : n;
        k_init<<<(total + 255) / 256, 256>>>(out, out_size, n);
    }

    // both degree counts, dual 3-phase scan (dinv fused in scan1), dual fill
    k_cnt_both<<<(e + 255) / 256, 256>>>(row, col, e);
    {
        int nb = (n + SCAN_B - 1) / SCAN_B;
        dim3 g1(nb, 2);
        k_scan1<<<g1, 1024>>>(n);
        k_scan2<<<2, 64>>>(n);
        k_scan3<<<g1, 1024>>>(n);
    }
    k_fill_both<<<(e + 255) / 256, 256>>>(row, col, e);

    // px = P @ x via col-CSR gather (self term + bias coef fused)
    k_gather_px<<<(n + 15) / 16, 256>>>(x, n);

    // FUSED assign-GEMM + softmax -> Sb (bf16); no f32 logits buffer
    k_xw1_sm<<<(n + 63) / 64, 256, SMEM_FUSED>>>(Wa, ba, n);

    // zE = px@We + c be^T  (f32)
    {
        dim3 g(1, (n + 63) / 64);
        k_xw0<<<g, 256>>>(We, be, n);
    }

    // AS = A @ S via row-CSR gather (bf16 in/out)
    k_AS_gather<<<(n + 3) / 4, 256>>>(n);

    // next_X = S^T @ zE  [K, C]  (bf16 S staged, f32x2 math)
    {
        int splits = 72;
        int nPer = (n + splits - 1) / splits;
        dim3 g(1, 4, splits);
        k_stm0<<<g, 256>>>(out, n, nPer);
    }
    // next_A = S^T @ AS  [K, K]  (bf16 mma)
    {
        int splits = 10;
        int nPer = (n + splits - 1) / splits;
        dim3 g(4, 4, splits);
        k_stm1<<<g, 256>>>(out + K * C, n, nPer);
    }
}

// round 17
// speedup vs baseline: 1.1424x; 1.1424x over previous
#include <cuda_runtime.h>
#include <cuda_bf16.h>
#include <math.h>
#include <stdint.h>

// Problem dims (fixed by dataset)
static constexpr int NMAX = 50000;
static constexpr int D    = 64;
static constexpr int C    = 64;   // embed out
static constexpr int K    = 500;  // assign out / clusters
static constexpr int KP   = 512;  // padded K
static constexpr int EMAX = 800000;
static constexpr int SCAN_B = 1024;
static constexpr int NSCANB = (NMAX + SCAN_B - 1) / SCAN_B;

// ---------------- scratch (device globals; no allocations allowed) ----------
// CSR pair: [0] = row-CSR (out-edges, stores col) for AS gather
//           [1] = col-CSR (in-edges, stores row) for px gather
__device__ float g_dinv[NMAX];
__device__ float g_c   [NMAX];
__device__ int   g_cnt [2][NMAX];
__device__ int   g_off [2][NMAX + 1];
__device__ int   g_cur [2][NMAX];
__device__ int   g_eidx[2][EMAX];
__device__ int   g_bsum[2][NSCANB];
__device__ int   g_bpre[2][NSCANB];
__device__ float g_px  [NMAX * D];                    // P @ x (f32)
__device__ float g_zE  [NMAX * C];                    // GCN(embed) f32 (stays f32!)
__device__ __nv_bfloat16 g_Sl [(long)NMAX * KP];      // assign logits*log2e (bf16)
__device__ __nv_bfloat16 g_Sb [(long)NMAX * KP];      // softmax bf16, padded
__device__ __nv_bfloat16 g_ASb[(long)NMAX * KP];      // A @ S bf16, padded

// ---------------- init: zero out + both cnt arrays --------------------------
__global__ void k_init(float* out, int total, int n) {
    int i = blockIdx.x * blockDim.x + threadIdx.x;
    if (i < total) out[i] = 0.0f;
    if (i < n) { g_cnt[0][i] = 0; g_cnt[1][i] = 0; }
}

__global__ void k_cnt_both(const int* __restrict__ row, const int* __restrict__ col,
                           int e) {
    int i = blockIdx.x * blockDim.x + threadIdx.x;
    if (i < e) {
        atomicAdd(&g_cnt[0][row[i]], 1);
        atomicAdd(&g_cnt[1][col[i]], 1);
    }
}

// ---------------- decoupled 3-phase exclusive scan (both arrays) ------------
__global__ __launch_bounds__(1024) void k_scan1(int n) {
    __shared__ int sm[1024];
    int a = blockIdx.y;
    int i = blockIdx.x * SCAN_B + threadIdx.x;
    int v = (i < n) ? g_cnt[a][i] : 0;
    if (a == 0 && i < n) g_dinv[i] = rsqrtf((float)v + 1.0f);
    sm[threadIdx.x] = v;
    __syncthreads();
#pragma unroll
    for (int off = 1; off < 1024; off <<= 1) {
        int u = (threadIdx.x >= off) ? sm[threadIdx.x - off] : 0;
        __syncthreads();
        sm[threadIdx.x] += u;
        __syncthreads();
    }
    if (i < n) g_off[a][i] = sm[threadIdx.x] - v;
    if (threadIdx.x == 1023) g_bsum[a][blockIdx.x] = sm[1023];
}

__global__ __launch_bounds__(64) void k_scan2(int n) {
    __shared__ int sm[64];
    int a = blockIdx.x;
    int t = threadIdx.x;
    int v = (t < NSCANB) ? g_bsum[a][t] : 0;
    sm[t] = v;
    __syncthreads();
#pragma unroll
    for (int off = 1; off < 64; off <<= 1) {
        int u = (t >= off) ? sm[t - off] : 0;
        __syncthreads();
        sm[t] += u;
        __syncthreads();
    }
    if (t < NSCANB) g_bpre[a][t] = sm[t] - v;
    if (t == 63) g_off[a][n] = sm[63];
}

__global__ __launch_bounds__(1024) void k_scan3(int n) {
    int a = blockIdx.y;
    int i = blockIdx.x * SCAN_B + threadIdx.x;
    if (i < n) {
        int o = g_off[a][i] + g_bpre[a][blockIdx.x];
        g_off[a][i] = o;
        g_cur[a][i] = o;
    }
}

// fill both CSRs in one pass
__global__ void k_fill_both(const int* __restrict__ row, const int* __restrict__ col,
                            int e) {
    int i = blockIdx.x * blockDim.x + threadIdx.x;
    if (i < e) {
        int r = row[i], c = col[i];
        int p0 = atomicAdd(&g_cur[0][r], 1);
        g_eidx[0][p0] = c;
        int p1 = atomicAdd(&g_cur[1][c], 1);
        g_eidx[1][p1] = r;
    }
}

// ---------------- px = P @ x via col-CSR gather (+ self term, + c coef) -----
__global__ __launch_bounds__(256) void k_gather_px(const float* __restrict__ x, int n) {
    int node = blockIdx.x * 16 + (threadIdx.x >> 4);
    if (node >= n) return;
    int lane = threadIdx.x & 15;
    float dv = g_dinv[node];
    int beg = g_off[1][node], end = g_off[1][node + 1];

    float4 acc = __ldg(reinterpret_cast<const float4*>(x + (long)node * D) + lane);
    acc.x *= dv; acc.y *= dv; acc.z *= dv; acc.w *= dv;
    float csum = dv;

    int e = beg;
    for (; e + 1 < end; e += 2) {
        int r0 = __ldg(&g_eidx[1][e]);
        int r1 = __ldg(&g_eidx[1][e + 1]);
        float w0 = __ldg(&g_dinv[r0]);
        float w1 = __ldg(&g_dinv[r1]);
        float4 v0 = __ldg(reinterpret_cast<const float4*>(x + (long)r0 * D) + lane);
        float4 v1 = __ldg(reinterpret_cast<const float4*>(x + (long)r1 * D) + lane);
        acc.x += w0 * v0.x + w1 * v1.x;
        acc.y += w0 * v0.y + w1 * v1.y;
        acc.z += w0 * v0.z + w1 * v1.z;
        acc.w += w0 * v0.w + w1 * v1.w;
        csum += w0 + w1;
    }
    if (e < end) {
        int r0 = __ldg(&g_eidx[1][e]);
        float w0 = __ldg(&g_dinv[r0]);
        float4 v0 = __ldg(reinterpret_cast<const float4*>(x + (long)r0 * D) + lane);
        acc.x += w0 * v0.x; acc.y += w0 * v0.y;
        acc.z += w0 * v0.z; acc.w += w0 * v0.w;
        csum += w0;
    }

    float4 o = make_float4(dv * acc.x, dv * acc.y, dv * acc.z, dv * acc.w);
    reinterpret_cast<float4*>(g_px + (long)node * D)[lane] = o;
    if (lane == 0) g_c[node] = dv * csum;
}

// ---------------- zE = px @ We + c*be^T  (f32x2 packed; f32 out) ------------
__global__ __launch_bounds__(256) void k_xw0(const float* __restrict__ W,
                                             const float* __restrict__ b, int n) {
    constexpr int TN = 4, PADX = 66;
    __shared__ float xs[64][PADX];
    __shared__ float ws[64][64];

    const int n0 = blockIdx.y * 64;
    const int tid = threadIdx.x;

    for (int i = tid; i < 64 * 16; i += 256) {
        int nn = i >> 4, k4 = (i & 15) << 2;
        float4 v = make_float4(0.f, 0.f, 0.f, 0.f);
        if (n0 + nn < n)
            v = *reinterpret_cast<const float4*>(g_px + (long)(n0 + nn) * D + k4);
        xs[k4 + 0][nn] = v.x; xs[k4 + 1][nn] = v.y;
        xs[k4 + 2][nn] = v.z; xs[k4 + 3][nn] = v.w;
    }
    for (int i = tid; i < 64 * 16; i += 256) {
        int k = i >> 4, c4 = (i & 15) << 2;
        *reinterpret_cast<float4*>(&ws[k][c4]) =
            *reinterpret_cast<const float4*>(W + k * C + c4);
    }
    __syncthreads();

    const int txm = tid & 15;
    const int tyn = tid >> 4;

    unsigned long long acc[2][TN];
#pragma unroll
    for (int p = 0; p < 2; p++)
#pragma unroll
        for (int j = 0; j < TN; j++) acc[p][j] = 0ull;

    uint32_t sX = (uint32_t)__cvta_generic_to_shared((void*)&xs[0][0]);

#pragma unroll 4
    for (int k = 0; k < 64; k++) {
        unsigned long long a2[2];
#pragma unroll
        for (int p = 0; p < 2; p++) {
            uint32_t addr = sX + ((uint32_t)(k * PADX + txm * 4 + p * 2) << 2);
            asm volatile("ld.shared.b64 %0, [%1];" : "=l"(a2[p]) : "r"(addr));
        }
        float bv[TN];
        float4 b4 = *reinterpret_cast<const float4*>(&ws[k][tyn * TN]);
        bv[0] = b4.x; bv[1] = b4.y; bv[2] = b4.z; bv[3] = b4.w;
#pragma unroll
        for (int j = 0; j < TN; j++) {
            unsigned long long bb;
            asm("mov.b64 %0, {%1, %2};" : "=l"(bb) : "f"(bv[j]), "f"(bv[j]));
#pragma unroll
            for (int p = 0; p < 2; p++)
                asm("fma.rn.f32x2 %0, %1, %2, %0;"
                    : "+l"(acc[p][j]) : "l"(a2[p]), "l"(bb));
        }
    }

#pragma unroll
    for (int p = 0; p < 2; p++) {
        int nn = n0 + txm * 4 + p * 2;
        float cv0 = (nn < n) ? g_c[nn] : 0.f;
        float cv1 = (nn + 1 < n) ? g_c[nn + 1] : 0.f;
#pragma unroll
        for (int j = 0; j < TN; j++) {
            int cc = tyn * TN + j;
            float lo, hi;
            asm("mov.b64 {%0, %1}, %2;" : "=f"(lo), "=f"(hi) : "l"(acc[p][j]));
            float bj = __ldg(&b[cc]);
            if (nn < n)     g_zE[(long)nn * C + cc] = lo + cv0 * bj;
            if (nn + 1 < n) g_zE[(long)(nn + 1) * C + cc] = hi + cv1 * bj;
        }
    }
}

// ---------------- logits = (px @ Wa + c*ba^T)*log2e  (FFMA2, bf16 OUT) ------
// f32 math throughout (inputs NOT quantized); only the final store rounds to
// bf16. Logit roundings are independent across (n,k) -> sqrt(N) suppression.
__global__ __launch_bounds__(256) void k_xw1(const float* __restrict__ W,
                                             const float* __restrict__ b, int n) {
    constexpr int BN = 128, TN = 8, PADX = 66;
    constexpr float LOG2E = 1.4426950408889634f;

    __shared__ float xs[64][PADX];       // [k][n], transposed px tile
    __shared__ float ws[64][BN];         // [k][c] * log2e

    const int n0 = blockIdx.y * 64;
    const int c0 = blockIdx.x * BN;
    const int tid = threadIdx.x;

    for (int i = tid; i < 64 * 16; i += 256) {
        int nn = i >> 4, k4 = (i & 15) << 2;
        float4 v = make_float4(0.f, 0.f, 0.f, 0.f);
        if (n0 + nn < n)
            v = *reinterpret_cast<const float4*>(g_px + (long)(n0 + nn) * D + k4);
        xs[k4 + 0][nn] = v.x; xs[k4 + 1][nn] = v.y;
        xs[k4 + 2][nn] = v.z; xs[k4 + 3][nn] = v.w;
    }
    for (int i = tid; i < 64 * (BN / 4); i += 256) {
        int k = i / (BN / 4), c4 = (i % (BN / 4)) << 2;
        int cc = c0 + c4;
        float4 v;
        if (cc + 3 < K) {
            v = *reinterpret_cast<const float4*>(W + k * K + cc);
        } else {
            float t0 = (cc + 0 < K) ? W[k * K + cc + 0] : 0.f;
            float t1 = (cc + 1 < K) ? W[k * K + cc + 1] : 0.f;
            float t2 = (cc + 2 < K) ? W[k * K + cc + 2] : 0.f;
            float t3 = (cc + 3 < K) ? W[k * K + cc + 3] : 0.f;
            v = make_float4(t0, t1, t2, t3);
        }
        v.x *= LOG2E; v.y *= LOG2E; v.z *= LOG2E; v.w *= LOG2E;
        *reinterpret_cast<float4*>(&ws[k][c4]) = v;
    }
    __syncthreads();

    const int txm = tid & 15;
    const int tyn = tid >> 4;

    unsigned long long acc[2][TN];
#pragma unroll
    for (int p = 0; p < 2; p++)
#pragma unroll
        for (int j = 0; j < TN; j++) acc[p][j] = 0ull;

    uint32_t sX = (uint32_t)__cvta_generic_to_shared((void*)&xs[0][0]);

#pragma unroll 4
    for (int k = 0; k < 64; k++) {
        unsigned long long a2[2];
#pragma unroll
        for (int p = 0; p < 2; p++) {
            uint32_t addr = sX + ((uint32_t)(k * PADX + txm * 4 + p * 2) << 2);
            asm volatile("ld.shared.b64 %0, [%1];" : "=l"(a2[p]) : "r"(addr));
        }
        float bv[TN];
#pragma unroll
        for (int j4 = 0; j4 < TN / 4; j4++) {
            float4 b4 = *reinterpret_cast<const float4*>(&ws[k][tyn * TN + j4 * 4]);
            bv[j4 * 4 + 0] = b4.x; bv[j4 * 4 + 1] = b4.y;
            bv[j4 * 4 + 2] = b4.z; bv[j4 * 4 + 3] = b4.w;
        }
#pragma unroll
        for (int j = 0; j < TN; j++) {
            unsigned long long bb;
            asm("mov.b64 %0, {%1, %2};" : "=l"(bb) : "f"(bv[j]), "f"(bv[j]));
#pragma unroll
            for (int p = 0; p < 2; p++)
                asm("fma.rn.f32x2 %0, %1, %2, %0;"
                    : "+l"(acc[p][j]) : "l"(a2[p]), "l"(bb));
        }
    }

    // epilogue: logits + c*b -> bf16, one uint4 store per row (8 cols)
#pragma unroll
    for (int p = 0; p < 2; p++) {
        int nn = n0 + txm * 4 + p * 2;
        float cv0 = (nn < n) ? g_c[nn] : 0.f;
        float cv1 = (nn + 1 < n) ? g_c[nn + 1] : 0.f;
        float lo[TN], hi[TN];
#pragma unroll
        for (int j = 0; j < TN; j++) {
            int cc = c0 + tyn * TN + j;
            float l, h;
            asm("mov.b64 {%0, %1}, %2;" : "=f"(l), "=f"(h) : "l"(acc[p][j]));
            float bj = (cc < K) ? __ldg(&b[cc]) * LOG2E : 0.f;
            lo[j] = l + cv0 * bj;
            hi[j] = h + cv1 * bj;
        }
        uint4 o0, o1;
#pragma unroll
        for (int q = 0; q < 4; q++) {
            __nv_bfloat162 r0 = __floats2bfloat162_rn(lo[2 * q], lo[2 * q + 1]);
            __nv_bfloat162 r1 = __floats2bfloat162_rn(hi[2 * q], hi[2 * q + 1]);
            (&o0.x)[q] = *reinterpret_cast<uint32_t*>(&r0);
            (&o1.x)[q] = *reinterpret_cast<uint32_t*>(&r1);
        }
        long base = (long)nn * KP + c0 + tyn * TN;
        if (nn < n)
            *reinterpret_cast<uint4*>(g_Sl + base) = o0;
        if (nn + 1 < n)
            *reinterpret_cast<uint4*>(g_Sl + base + KP) = o1;
    }
}

// ---------------- row softmax: bf16 log2-domain logits -> g_Sb (bf16) -------
// warp per row; lane owns cols [lane*16, lane*16+16). No max subtraction
// (logits bounded). Padding cols >= 500 masked before exp.
__global__ __launch_bounds__(256) void k_softmax(int n) {
    int row = blockIdx.x * 8 + (threadIdx.x >> 5);
    int lane = threadIdx.x & 31;
    if (row >= n) return;
    const uint4* p = reinterpret_cast<const uint4*>(g_Sl + (long)row * KP);

    uint4 v0 = __ldg(&p[lane * 2]);
    uint4 v1 = __ldg(&p[lane * 2 + 1]);
    float f[16];
#pragma unroll
    for (int q = 0; q < 4; q++) {
        uint32_t w0 = (&v0.x)[q], w1 = (&v1.x)[q];
        float2 a = __bfloat1622float2(*reinterpret_cast<__nv_bfloat162*>(&w0));
        float2 d = __bfloat1622float2(*reinterpret_cast<__nv_bfloat162*>(&w1));
        f[q * 2 + 0] = a.x; f[q * 2 + 1] = a.y;
        f[8 + q * 2 + 0] = d.x; f[8 + q * 2 + 1] = d.y;
    }
    if (lane == 31) {   // cols 496..511; only c<500 valid -> elems >=4 padding
#pragma unroll
        for (int i = 4; i < 16; i++) f[i] = -1e30f;
    }

    float r[16];
#pragma unroll
    for (int i = 0; i < 16; i++)
        asm("ex2.approx.ftz.f32 %0, %1;" : "=f"(r[i]) : "f"(f[i]));

    float sum = 0.0f;
#pragma unroll
    for (int i = 0; i < 16; i++) sum += r[i];
#pragma unroll
    for (int off = 16; off > 0; off >>= 1)
        sum += __shfl_xor_sync(0xffffffffu, sum, off);

    float inv = 1.0f / sum;

    uint32_t ob[8];
#pragma unroll
    for (int q = 0; q < 8; q++) {
        __nv_bfloat162 rb = __floats2bfloat162_rn(r[2 * q] * inv, r[2 * q + 1] * inv);
        ob[q] = *reinterpret_cast<uint32_t*>(&rb);
    }
    uint4* dst = reinterpret_cast<uint4*>(g_Sb) + (long)row * (KP / 8) + lane * 2;
    dst[0] = make_uint4(ob[0], ob[1], ob[2], ob[3]);
    dst[1] = make_uint4(ob[4], ob[5], ob[6], ob[7]);
}

// ---------------- AS[i] = sum_{e in out(i)} Sb[col_e]  (bf16 in/out) --------
__global__ __launch_bounds__(256) void k_AS_gather(int n) {
    int node = blockIdx.x * 4 + (threadIdx.x >> 6);
    if (node >= n) return;
    int c = threadIdx.x & 63;
    int beg = g_off[0][node], end = g_off[0][node + 1];

    float a[8] = {};
    const uint4* base = reinterpret_cast<const uint4*>(g_Sb);

    int e = beg;
    for (; e + 3 < end; e += 4) {
        int s0 = __ldg(&g_eidx[0][e]);
        int s1 = __ldg(&g_eidx[0][e + 1]);
        int s2 = __ldg(&g_eidx[0][e + 2]);
        int s3 = __ldg(&g_eidx[0][e + 3]);
        uint4 v0 = __ldg(&base[(long)s0 * (KP / 8) + c]);
        uint4 v1 = __ldg(&base[(long)s1 * (KP / 8) + c]);
        uint4 v2 = __ldg(&base[(long)s2 * (KP / 8) + c]);
        uint4 v3 = __ldg(&base[(long)s3 * (KP / 8) + c]);
#pragma unroll
        for (int q = 0; q < 4; q++) {
            uint32_t w0 = (&v0.x)[q], w1 = (&v1.x)[q];
            uint32_t w2 = (&v2.x)[q], w3 = (&v3.x)[q];
            float2 f0 = __bfloat1622float2(*reinterpret_cast<__nv_bfloat162*>(&w0));
            float2 f1 = __bfloat1622float2(*reinterpret_cast<__nv_bfloat162*>(&w1));
            float2 f2 = __bfloat1622float2(*reinterpret_cast<__nv_bfloat162*>(&w2));
            float2 f3 = __bfloat1622float2(*reinterpret_cast<__nv_bfloat162*>(&w3));
            a[q * 2 + 0] += (f0.x + f1.x) + (f2.x + f3.x);
            a[q * 2 + 1] += (f0.y + f1.y) + (f2.y + f3.y);
        }
    }
    for (; e < end; e++) {
        int s0 = __ldg(&g_eidx[0][e]);
        uint4 v0 = __ldg(&base[(long)s0 * (KP / 8) + c]);
#pragma unroll
        for (int q = 0; q < 4; q++) {
            uint32_t w0 = (&v0.x)[q];
            float2 f0 = __bfloat1622float2(*reinterpret_cast<__nv_bfloat162*>(&w0));
            a[q * 2 + 0] += f0.x;
            a[q * 2 + 1] += f0.y;
        }
    }

    uint4 o;
#pragma unroll
    for (int q = 0; q < 4; q++) {
        __nv_bfloat162 r = __floats2bfloat162_rn(a[q * 2], a[q * 2 + 1]);
        (&o.x)[q] = *reinterpret_cast<uint32_t*>(&r);
    }
    reinterpret_cast<uint4*>(g_ASb)[(long)node * (KP / 8) + c] = o;
}

// ---------------- next_X = S^T @ zE  (bf16 S staged to f32, f32x2 math) -----
__global__ __launch_bounds__(256) void k_stm0(float* __restrict__ out, int n,
                                              int nPerSplit) {
    constexpr int BN = 64, TN = 4, BM = 128, BK = 32;
    __shared__ float Ss[BK][BM];
    __shared__ float Ms[BK][BN];

    const int m0 = blockIdx.y * BM;
    const int nStart = blockIdx.z * nPerSplit;
    const int nEnd = min(n, nStart + nPerSplit);
    const int tid = threadIdx.x;
    const int txm = tid & 15;
    const int tyn = tid >> 4;

    unsigned long long acc[2][2][TN];
#pragma unroll
    for (int a = 0; a < 2; a++)
#pragma unroll
        for (int p = 0; p < 2; p++)
#pragma unroll
            for (int j = 0; j < TN; j++) acc[a][p][j] = 0ull;

    uint32_t sS = (uint32_t)__cvta_generic_to_shared((void*)&Ss[0][0]);

    for (int nb = nStart; nb < nEnd; nb += BK) {
        for (int i = tid; i < BK * (BM / 8); i += 256) {
            int r = i >> 4, q = i & 15;
            int kk = nb + r;
            uint4 v = make_uint4(0, 0, 0, 0);
            if (kk < nEnd)
                v = *reinterpret_cast<const uint4*>(g_Sb + (long)kk * KP + m0 + q * 8);
            float fx[8];
#pragma unroll
            for (int w = 0; w < 4; w++) {
                float2 ff = __bfloat1622float2(
                    *reinterpret_cast<__nv_bfloat162*>(&(&v.x)[w]));
                fx[w * 2] = ff.x; fx[w * 2 + 1] = ff.y;
            }
            *reinterpret_cast<float4*>(&Ss[r][q * 8]) =
                make_float4(fx[0], fx[1], fx[2], fx[3]);
            *reinterpret_cast<float4*>(&Ss[r][q * 8 + 4]) =
                make_float4(fx[4], fx[5], fx[6], fx[7]);
        }
        for (int i = tid; i < BK * (BN / 4); i += 256) {
            int r = i / (BN / 4);
            int c4 = i % (BN / 4);
            int kk = nb + r;
            float4 v = make_float4(0.f, 0.f, 0.f, 0.f);
            if (kk < nEnd)
                v = *reinterpret_cast<const float4*>(g_zE + (long)kk * C + (c4 << 2));
            *reinterpret_cast<float4*>(&Ms[r][c4 << 2]) = v;
        }
        __syncthreads();

#pragma unroll 8
        for (int kk = 0; kk < BK; kk++) {
            unsigned long long a2[2][2];
#pragma unroll
            for (int ch = 0; ch < 2; ch++)
#pragma unroll
                for (int p = 0; p < 2; p++) {
                    uint32_t addr = sS + ((kk * BM + ch * 64 + txm * 4 + p * 2) << 2);
                    asm volatile("ld.shared.b64 %0, [%1];" : "=l"(a2[ch][p]) : "r"(addr));
                }
            float bv[TN];
            float4 b4 = *reinterpret_cast<const float4*>(&Ms[kk][tyn * TN]);
            bv[0] = b4.x; bv[1] = b4.y; bv[2] = b4.z; bv[3] = b4.w;
#pragma unroll
            for (int j = 0; j < TN; j++) {
                unsigned long long bb;
                asm("mov.b64 %0, {%1, %2};" : "=l"(bb) : "f"(bv[j]), "f"(bv[j]));
#pragma unroll
                for (int ch = 0; ch < 2; ch++)
#pragma unroll
                    for (int p = 0; p < 2; p++)
                        asm("fma.rn.f32x2 %0, %1, %2, %0;"
                            : "+l"(acc[ch][p][j]) : "l"(a2[ch][p]), "l"(bb));
            }
        }
        __syncthreads();
    }

#pragma unroll
    for (int ch = 0; ch < 2; ch++)
#pragma unroll
        for (int p = 0; p < 2; p++)
#pragma unroll
            for (int j = 0; j < TN; j++) {
                float lo, hi;
                asm("mov.b64 {%0, %1}, %2;" : "=f"(lo), "=f"(hi) : "l"(acc[ch][p][j]));
                int m = m0 + ch * 64 + txm * 4 + p * 2;
                int nn = tyn * TN + j;
                if (m < K)     atomicAdd(&out[(long)m * C + nn], lo);
                if (m + 1 < K) atomicAdd(&out[(long)(m + 1) * C + nn], hi);
            }
}

// ---------------- next_A = S^T @ AS  (bf16 mma.sync, split-K) ---------------
__global__ __launch_bounds__(256) void k_stm1(float* __restrict__ out, int n,
                                              int nPerSplit) {
    constexpr int PAD = 136;
    __shared__ __align__(16) __nv_bfloat16 As[32][PAD];
    __shared__ __align__(16) __nv_bfloat16 Bs[32][PAD];

    const int m0 = blockIdx.y * 128;
    const int n0 = blockIdx.x * 128;
    const int nStart = blockIdx.z * nPerSplit;
    const int nEnd = min(n, nStart + nPerSplit);
    const int tid = threadIdx.x;
    const int wid = tid >> 5, lane = tid & 31;
    const int wm = wid & 1, wn = wid >> 1;

    float acc[4][4][4] = {};

    uint32_t sA = (uint32_t)__cvta_generic_to_shared((void*)&As[0][0]);
    uint32_t sB = (uint32_t)__cvta_generic_to_shared((void*)&Bs[0][0]);

    for (int k0 = nStart; k0 < nEnd; k0 += 32) {
#pragma unroll
        for (int i = tid; i < 32 * 16; i += 256) {
            int r = i >> 4, q = i & 15;
            int kk = k0 + r;
            uint4 v = make_uint4(0, 0, 0, 0);
            if (kk < nEnd)
                v = *reinterpret_cast<const uint4*>(g_Sb + (long)kk * KP + m0 + q * 8);
            *reinterpret_cast<uint4*>(&As[r][q * 8]) = v;
        }
#pragma unroll
        for (int i = tid; i < 32 * 16; i += 256) {
            int r = i >> 4, q = i & 15;
            int kk = k0 + r;
            uint4 v = make_uint4(0, 0, 0, 0);
            if (kk < nEnd)
                v = *reinterpret_cast<const uint4*>(g_ASb + (long)kk * KP + n0 + q * 8);
            *reinterpret_cast<uint4*>(&Bs[r][q * 8]) = v;
        }
        __syncthreads();

#pragma unroll
        for (int s = 0; s < 2; s++) {
            uint32_t af[4][4];
            int ra = s * 16 + (lane & 7) + ((lane >> 4) << 3);
            int ca = wm * 64 + (((lane >> 3) & 1) << 3);
#pragma unroll
            for (int t = 0; t < 4; t++) {
                uint32_t addr = sA + (uint32_t)(ra * PAD + ca + t * 16) * 2;
                asm volatile("ldmatrix.sync.aligned.m8n8.x4.trans.shared.b16 "
                             "{%0,%1,%2,%3}, [%4];"
                             : "=r"(af[t][0]), "=r"(af[t][1]), "=r"(af[t][2]), "=r"(af[t][3])
                             : "r"(addr));
            }
            uint32_t bfr[2][4];
            int rb = s * 16 + (lane & 7) + (((lane >> 3) & 1) << 3);
            int cb = wn * 32 + ((lane >> 4) << 3);
#pragma unroll
            for (int g = 0; g < 2; g++) {
                uint32_t addr = sB + (uint32_t)(rb * PAD + cb + g * 16) * 2;
                asm volatile("ldmatrix.sync.aligned.m8n8.x4.trans.shared.b16 "
                             "{%0,%1,%2,%3}, [%4];"
                             : "=r"(bfr[g][0]), "=r"(bfr[g][1]), "=r"(bfr[g][2]), "=r"(bfr[g][3])
                             : "r"(addr));
            }
#pragma unroll
            for (int t = 0; t < 4; t++)
#pragma unroll
                for (int j = 0; j < 4; j++) {
                    uint32_t b0 = bfr[j >> 1][(j & 1) * 2];
                    uint32_t b1 = bfr[j >> 1][(j & 1) * 2 + 1];
                    asm volatile(
                        "mma.sync.aligned.m16n8k16.row.col.f32.bf16.bf16.f32 "
                        "{%0,%1,%2,%3}, {%4,%5,%6,%7}, {%8,%9}, {%0,%1,%2,%3};"
                        : "+f"(acc[t][j][0]), "+f"(acc[t][j][1]),
                          "+f"(acc[t][j][2]), "+f"(acc[t][j][3])
                        : "r"(af[t][0]), "r"(af[t][1]), "r"(af[t][2]), "r"(af[t][3]),
                          "r"(b0), "r"(b1));
                }
        }
        __syncthreads();
    }

#pragma unroll
    for (int t = 0; t < 4; t++) {
        int mA = m0 + wm * 64 + t * 16 + (lane >> 2);
#pragma unroll
        for (int j = 0; j < 4; j++) {
            int nn = n0 + wn * 32 + j * 8 + (lane & 3) * 2;
            if (nn < K) {
                if (mA < K)     atomicAdd(&out[(long)mA * K + nn], acc[t][j][0]);
                if (mA + 8 < K) atomicAdd(&out[(long)(mA + 8) * K + nn], acc[t][j][2]);
            }
            if (nn + 1 < K) {
                if (mA < K)     atomicAdd(&out[(long)mA * K + nn + 1], acc[t][j][1]);
                if (mA + 8 < K) atomicAdd(&out[(long)(mA + 8) * K + nn + 1], acc[t][j][3]);
            }
        }
    }
}

// ---------------- launch -----------------------------------------------------
extern "C" void kernel_launch(void* const* d_in, const int* in_sizes, int n_in,
                              void* d_out, int out_size) {
    const float* x  = (const float*)d_in[0];
    const int*   ei = (const int*)d_in[1];
    const float* We = (const float*)d_in[2];
    const float* be = (const float*)d_in[3];
    const float* Wa = (const float*)d_in[4];
    const float* ba = (const float*)d_in[5];
    float* out = (float*)d_out;

    int n = in_sizes[0] / D;
    int e = in_sizes[1] / 2;
    const int* row = ei;       // source j
    const int* col = ei + e;   // target i

    // init: zero output + both cnt arrays
    {
        int total = out_size > n ? out_size : n;
        k_init<<<(total + 255) / 256, 256>>>(out, out_size, n);
    }

    // both degree counts, dual 3-phase scan (dinv fused in scan1), dual fill
    k_cnt_both<<<(e + 255) / 256, 256>>>(row, col, e);
    {
        int nb = (n + SCAN_B - 1) / SCAN_B;
        dim3 g1(nb, 2);
        k_scan1<<<g1, 1024>>>(n);
        k_scan2<<<2, 64>>>(n);
        k_scan3<<<g1, 1024>>>(n);
    }
    k_fill_both<<<(e + 255) / 256, 256>>>(row, col, e);

    // px = P @ x via col-CSR gather (self term + bias coef fused)
    k_gather_px<<<(n + 15) / 16, 256>>>(x, n);

    // logits = (px@Wa + c ba^T)*log2e  (f32 FFMA2 math; bf16 STORE only)
    {
        dim3 gA((K + 127) / 128, (n + 63) / 64);
        k_xw1<<<gA, 256>>>(Wa, ba, n);
    }
    // zE = px@We + c be^T  (f32x2, f32 out — stays f32)
    {
        dim3 g(1, (n + 63) / 64);
        k_xw0<<<g, 256>>>(We, be, n);
    }

    // softmax: bf16 log2 logits -> Sb (bf16)
    k_softmax<<<(n + 7) / 8, 256>>>(n);

    // AS = A @ S via row-CSR gather (bf16 in/out)
    k_AS_gather<<<(n + 3) / 4, 256>>>(n);

    // next_X = S^T @ zE  [K, C]  (bf16 S staged, f32x2 math)
    {
        int splits = 72;
        int nPer = (n + splits - 1) / splits;
        dim3 g(1, 4, splits);
        k_stm0<<<g, 256>>>(out, n, nPer);
    }
    // next_A = S^T @ AS  [K, K]  (bf16 mma)
    {
        int splits = 10;
        int nPer = (n + splits - 1) / splits;
        dim3 g(4, 4, splits);
        k_stm1<<<g, 256>>>(out + K * C, n, nPer);
    }
}